// round 1
// baseline (speedup 1.0000x reference)
#include <cuda_runtime.h>

// Problem constants
#define N_NODES 4096
#define FEAT    32
#define G3      192      // 3*H
#define HDIM    64
#define BATCH   4
#define TSTEPS  8
#define MAXD    128      // ELL max degree (avg ~32, max ~55 expected)
#define NPB     64       // nodes per block in fused kernel
#define THREADS 256
#define NROWS   (BATCH*TSTEPS*N_NODES)   // 131072 rows of F features
#define NB_STAT 128

// -------- device scratch (static, allocation-free) --------
__device__ int   g_row_len[N_NODES];
__device__ float g_row_wsum[N_NODES];
__device__ int   g_ell_col[N_NODES * MAXD];
__device__ float g_ell_val[N_NODES * MAXD];
__device__ float g_bnA[FEAT];
__device__ float g_bnC[FEAT];
__device__ float g_Wcomb[FEAT * G3];
__device__ float g_bcomb[G3];
__device__ float g_part[NB_STAT * 64];

// ============================================================
// Kernel 1: BN partial sums (deterministic two-pass reduction)
// lane <-> feature; each warp strides over rows.
// ============================================================
__global__ void bn_partial_kernel(const float* __restrict__ x)
{
    const int lane = threadIdx.x & 31;
    const int gw   = (blockIdx.x * blockDim.x + threadIdx.x) >> 5;  // 0..1023
    float s = 0.f, q = 0.f;
    for (int r = gw; r < NROWS; r += (NB_STAT * THREADS) / 32) {
        float v = x[(size_t)r * FEAT + lane];
        s += v;
        q += v * v;
    }
    __shared__ float sh[8][64];
    const int w = threadIdx.x >> 5;
    sh[w][lane]      = s;
    sh[w][32 + lane] = q;
    __syncthreads();
    if (threadIdx.x < 64) {
        float a = 0.f;
        #pragma unroll
        for (int i = 0; i < 8; ++i) a += sh[i][threadIdx.x];
        g_part[blockIdx.x * 64 + threadIdx.x] = a;
    }
}

// ============================================================
// Kernel 2: finalize BN affine + Wcomb = W_gcn@W_ih, bcomb
// ============================================================
__global__ void bn_finalize_kernel(const float* __restrict__ gamma,
                                   const float* __restrict__ beta,
                                   const float* __restrict__ Wgcn,
                                   const float* __restrict__ bgcn,
                                   const float* __restrict__ Wih,
                                   const float* __restrict__ bih)
{
    __shared__ float s_sum[32], s_sq[32];
    const int tid = threadIdx.x;
    if (tid < 64) {
        float a = 0.f;
        for (int bk = 0; bk < NB_STAT; ++bk) a += g_part[bk * 64 + tid];
        if (tid < 32) s_sum[tid] = a; else s_sq[tid - 32] = a;
    }
    __syncthreads();
    if (tid < 32) {
        const float M    = (float)NROWS;
        const float mean = s_sum[tid] / M;
        const float var  = s_sq[tid] / M - mean * mean;
        const float aK   = gamma[tid] * (1.0f / sqrtf(var + 1e-5f));
        g_bnA[tid] = aK;
        g_bnC[tid] = beta[tid] - mean * aK;
    }
    // Wcomb[f][j] = sum_c Wgcn[f][c] * Wih[c][j]
    for (int idx = tid; idx < FEAT * G3; idx += blockDim.x) {
        const int f = idx / G3, j = idx % G3;
        float acc = 0.f;
        #pragma unroll 8
        for (int c = 0; c < 32; ++c) acc += Wgcn[f * 32 + c] * Wih[c * G3 + j];
        g_Wcomb[idx] = acc;
    }
    if (tid < G3) {
        float acc = bih[tid];
        #pragma unroll 8
        for (int c = 0; c < 32; ++c) acc += bgcn[c] * Wih[c * G3 + tid];
        g_bcomb[tid] = acc;
    }
}

// ============================================================
// Kernel 3: dense adj -> ELL via ballot compaction (deterministic,
// single pass, column-sorted order).  One warp per row.
// ============================================================
__global__ void build_ell_kernel(const float* __restrict__ adj)
{
    const int warp = (blockIdx.x * blockDim.x + threadIdx.x) >> 5;  // 0..4095
    const int lane = threadIdx.x & 31;
    const float* row = adj + (size_t)warp * N_NODES;
    const int base = warp * MAXD;
    int   cnt  = 0;
    float wsum = 0.f;
    for (int i = 0; i < N_NODES / 32; ++i) {
        const int c = i * 32 + lane;
        const float v = row[c];
        wsum += v;
        const unsigned mask = __ballot_sync(0xffffffffu, v != 0.0f);
        if (v != 0.0f) {
            const int pos = cnt + __popc(mask & ((1u << lane) - 1u));
            if (pos < MAXD) {
                g_ell_col[base + pos] = c;
                g_ell_val[base + pos] = v;
            }
        }
        cnt += __popc(mask);
    }
    #pragma unroll
    for (int o = 16; o > 0; o >>= 1) wsum += __shfl_xor_sync(0xffffffffu, wsum, o);
    if (lane == 0) {
        g_row_len[warp]  = cnt < MAXD ? cnt : MAXD;
        g_row_wsum[warp] = wsum;
    }
}

// ============================================================
// Kernel 4: fused  BN-affine -> SpMM -> (ya@Wcomb) -> GRU -> dense
// One block = 64 nodes of one batch across all T=8 steps.
// Thread tile: 4 nodes x 4 h-dims x 3 gates (gi + gh accumulators).
// ============================================================
__device__ __forceinline__ float sigm(float v) {
    return 1.0f / (1.0f + __expf(-v));
}

#define GEMM_STEP(ACC, G, BB, A0, A1, A2, A3)                                     \
    ACC[G][0][0] += BB.x * A0; ACC[G][0][1] += BB.x * A1;                         \
    ACC[G][0][2] += BB.x * A2; ACC[G][0][3] += BB.x * A3;                         \
    ACC[G][1][0] += BB.y * A0; ACC[G][1][1] += BB.y * A1;                         \
    ACC[G][1][2] += BB.y * A2; ACC[G][1][3] += BB.y * A3;                         \
    ACC[G][2][0] += BB.z * A0; ACC[G][2][1] += BB.z * A1;                         \
    ACC[G][2][2] += BB.z * A2; ACC[G][2][3] += BB.z * A3;                         \
    ACC[G][3][0] += BB.w * A0; ACC[G][3][1] += BB.w * A1;                         \
    ACC[G][3][2] += BB.w * A2; ACC[G][3][3] += BB.w * A3;

__global__ void __launch_bounds__(THREADS, 1)
fused_gru_kernel(const float* __restrict__ x,
                 const float* __restrict__ Whh,
                 const float* __restrict__ bhh,
                 const float* __restrict__ Wd,
                 const float* __restrict__ bd,
                 float* __restrict__ out)
{
    extern __shared__ float sm[];
    float* sWhh = sm;                      // 64*192  = 12288
    float* sWc  = sWhh + HDIM * G3;        // 32*192  =  6144
    float* shT  = sWc  + FEAT * G3;        // h^T [c][m] 64*64 = 4096
    float* sYa  = shT  + HDIM * NPB;       // ya^T [f][m] 32*65 = 2080 (padded)
    float* sWd  = sYa  + FEAT * 65;        // 64

    const int tid  = threadIdx.x;
    const int b    = blockIdx.x >> 6;
    const int gm0  = (blockIdx.x & 63) * NPB;

    for (int i = tid; i < HDIM * G3; i += THREADS) sWhh[i] = Whh[i];
    for (int i = tid; i < FEAT * G3; i += THREADS) sWc[i]  = g_Wcomb[i];
    for (int i = tid; i < HDIM * NPB; i += THREADS) shT[i] = 0.0f;    // h0 = 0
    if (tid < HDIM) sWd[tid] = Wd[tid];

    const int mt = tid & 15;     // node-tile index
    const int kt = tid >> 4;     // hdim-tile index
    const int m0 = mt * 4;
    const int k0 = kt * 4;
    const int lane = tid & 31;
    const int wid  = tid >> 5;

    float biasA[3][4], biasB[3][4];
    #pragma unroll
    for (int g = 0; g < 3; ++g)
        #pragma unroll
        for (int kk = 0; kk < 4; ++kk) {
            biasA[g][kk] = g_bcomb[g * 64 + k0 + kk];
            biasB[g][kk] = bhh[g * 64 + k0 + kk];
        }
    const float bnA = g_bnA[lane];
    const float bnC = g_bnC[lane];
    const float bdv = bd[0];

    __syncthreads();

    for (int t = 0; t < TSTEPS; ++t) {
        const float* xbt = x + ((size_t)(b * TSTEPS + t) * N_NODES) * FEAT;

        // ---- aggregation: warp 'wid' handles 8 nodes, lane = feature ----
        #pragma unroll 1
        for (int mm = 0; mm < 8; ++mm) {
            const int m  = wid * 8 + mm;
            const int gm = gm0 + m;
            const int len = g_row_len[gm];
            const int*   cp = g_ell_col + gm * MAXD;
            const float* vp = g_ell_val + gm * MAXD;
            float a0 = 0.f, a1 = 0.f;
            int k = 0;
            for (; k + 1 < len; k += 2) {
                const int   c0 = cp[k],     c1 = cp[k + 1];
                const float w0 = vp[k],     w1 = vp[k + 1];
                a0 += w0 * xbt[c0 * FEAT + lane];
                a1 += w1 * xbt[c1 * FEAT + lane];
            }
            if (k < len) a0 += vp[k] * xbt[cp[k] * FEAT + lane];
            sYa[lane * 65 + m] = bnA * (a0 + a1) + bnC * g_row_wsum[gm];
        }
        __syncthreads();

        // ---- register-tiled GEMMs: gi = ya@Wcomb, gh = h@Whh ----
        float gi[3][4][4], gh[3][4][4];
        #pragma unroll
        for (int g = 0; g < 3; ++g)
            #pragma unroll
            for (int kk = 0; kk < 4; ++kk)
                #pragma unroll
                for (int mm = 0; mm < 4; ++mm) {
                    gi[g][kk][mm] = biasA[g][kk];
                    gh[g][kk][mm] = biasB[g][kk];
                }

        const float* yap = sYa + m0;
        #pragma unroll 4
        for (int f = 0; f < FEAT; ++f) {
            const float a0 = yap[f * 65 + 0];
            const float a1 = yap[f * 65 + 1];
            const float a2 = yap[f * 65 + 2];
            const float a3 = yap[f * 65 + 3];
            const float* wrow = sWc + f * G3 + k0;
            {
                const float4 bb = *(const float4*)(wrow);
                GEMM_STEP(gi, 0, bb, a0, a1, a2, a3)
            }
            {
                const float4 bb = *(const float4*)(wrow + 64);
                GEMM_STEP(gi, 1, bb, a0, a1, a2, a3)
            }
            {
                const float4 bb = *(const float4*)(wrow + 128);
                GEMM_STEP(gi, 2, bb, a0, a1, a2, a3)
            }
        }

        #pragma unroll 4
        for (int c = 0; c < HDIM; ++c) {
            const float4 aa = *(const float4*)(shT + c * NPB + m0);
            const float* wrow = sWhh + c * G3 + k0;
            {
                const float4 bb = *(const float4*)(wrow);
                GEMM_STEP(gh, 0, bb, aa.x, aa.y, aa.z, aa.w)
            }
            {
                const float4 bb = *(const float4*)(wrow + 64);
                GEMM_STEP(gh, 1, bb, aa.x, aa.y, aa.z, aa.w)
            }
            {
                const float4 bb = *(const float4*)(wrow + 128);
                GEMM_STEP(gh, 2, bb, aa.x, aa.y, aa.z, aa.w)
            }
        }

        // ---- GRU gates (fully thread-local) ----
        float hn[4][4];
        #pragma unroll
        for (int kk = 0; kk < 4; ++kk)
            #pragma unroll
            for (int mm = 0; mm < 4; ++mm) {
                const float hold = shT[(k0 + kk) * NPB + m0 + mm];
                const float r = sigm(gi[0][kk][mm] + gh[0][kk][mm]);
                const float z = sigm(gi[1][kk][mm] + gh[1][kk][mm]);
                const float n = tanhf(gi[2][kk][mm] + r * gh[2][kk][mm]);
                hn[kk][mm] = (1.0f - z) * n + z * hold;
            }
        __syncthreads();   // all GEMM reads of shT done
        #pragma unroll
        for (int kk = 0; kk < 4; ++kk) {
            float4 v;
            v.x = hn[kk][0]; v.y = hn[kk][1]; v.z = hn[kk][2]; v.w = hn[kk][3];
            *(float4*)(shT + (k0 + kk) * NPB + m0) = v;
        }
        __syncthreads();   // new h visible

        // ---- dense head: out = h @ W_dense + b ----
        if (tid < NPB) {
            float acc = bdv;
            #pragma unroll 8
            for (int k = 0; k < HDIM; ++k) acc += shT[k * NPB + tid] * sWd[k];
            out[(size_t)(b * TSTEPS + t) * N_NODES + gm0 + tid] = acc;
        }
        __syncthreads();
    }
}

// ============================================================
// launch
// ============================================================
extern "C" void kernel_launch(void* const* d_in, const int* in_sizes, int n_in,
                              void* d_out, int out_size)
{
    const float* x     = (const float*)d_in[0];
    const float* adj   = (const float*)d_in[1];
    const float* gamma = (const float*)d_in[2];
    const float* beta  = (const float*)d_in[3];
    const float* Wgcn  = (const float*)d_in[4];
    const float* bgcn  = (const float*)d_in[5];
    const float* Wih   = (const float*)d_in[6];
    const float* Whh   = (const float*)d_in[7];
    const float* bih   = (const float*)d_in[8];
    const float* bhh   = (const float*)d_in[9];
    const float* Wd    = (const float*)d_in[10];
    const float* bd    = (const float*)d_in[11];
    float* out = (float*)d_out;

    const int smem_bytes = (HDIM * G3 + FEAT * G3 + HDIM * NPB + FEAT * 65 + HDIM) * (int)sizeof(float);
    cudaFuncSetAttribute(fused_gru_kernel, cudaFuncAttributeMaxDynamicSharedMemorySize, smem_bytes);

    bn_partial_kernel<<<NB_STAT, THREADS>>>(x);
    bn_finalize_kernel<<<1, THREADS>>>(gamma, beta, Wgcn, bgcn, Wih, bih);
    build_ell_kernel<<<(N_NODES * 32) / THREADS, THREADS>>>(adj);
    fused_gru_kernel<<<BATCH * (N_NODES / NPB), THREADS, smem_bytes>>>(x, Whh, bhh, Wd, bd, out);
}

// round 2
// speedup vs baseline: 1.0274x; 1.0274x over previous
#include <cuda_runtime.h>

#define N_NODES 4096
#define FEAT    32
#define G3      192
#define HDIM    64
#define BATCH   4
#define TSTEPS  8
#define NBT     (BATCH*TSTEPS)           // 32
#define MAXD    128
#define NPB     64
#define THREADS 256
#define NROWS   (NBT*N_NODES)            // 131072
#define NB_STAT 128
#define SA_STRIDE 68                      // 96 x 68 fp32, 16B-aligned rows, conflict-free

// -------- static device scratch --------
__device__ int   g_row_len[N_NODES];
__device__ float g_row_wsum[N_NODES];
__device__ int2  g_ell_cv[N_NODES * MAXD];      // {col, val-as-bits}
__device__ float g_bnA[FEAT];
__device__ float g_bnC[FEAT];
__device__ float g_Wcomb[FEAT * G3];
__device__ float g_bcomb[G3];
__device__ float g_part[NB_STAT * 64];
__device__ float g_ya[(size_t)NROWS * FEAT];    // 16 MB aggregated input

// -------- f32x2 helpers --------
__device__ __forceinline__ unsigned long long pack2(float a) {
    unsigned long long r;
    asm("mov.b64 %0, {%1, %1};" : "=l"(r) : "f"(a));
    return r;
}
__device__ __forceinline__ float2 unpack2(unsigned long long v) {
    float2 r;
    asm("mov.b64 {%0, %1}, %2;" : "=f"(r.x), "=f"(r.y) : "l"(v));
    return r;
}
__device__ __forceinline__ unsigned long long fma2(unsigned long long a,
                                                   unsigned long long b,
                                                   unsigned long long c) {
    unsigned long long d;
    asm("fma.rn.f32x2 %0, %1, %2, %3;" : "=l"(d) : "l"(a), "l"(b), "l"(c));
    return d;
}
__device__ __forceinline__ float sigm(float v) { return 1.0f / (1.0f + __expf(-v)); }

// ============================================================
// Kernel 1: BN partial sums
// ============================================================
__global__ void bn_partial_kernel(const float* __restrict__ x)
{
    const int lane = threadIdx.x & 31;
    const int gw   = (blockIdx.x * blockDim.x + threadIdx.x) >> 5;
    float s = 0.f, q = 0.f;
    for (int r = gw; r < NROWS; r += (NB_STAT * THREADS) / 32) {
        float v = x[(size_t)r * FEAT + lane];
        s += v; q += v * v;
    }
    __shared__ float sh[8][64];
    const int w = threadIdx.x >> 5;
    sh[w][lane] = s; sh[w][32 + lane] = q;
    __syncthreads();
    if (threadIdx.x < 64) {
        float a = 0.f;
        #pragma unroll
        for (int i = 0; i < 8; ++i) a += sh[i][threadIdx.x];
        g_part[blockIdx.x * 64 + threadIdx.x] = a;
    }
}

// ============================================================
// Kernel 2: finalize BN affine + Wcomb/bcomb
// ============================================================
__global__ void bn_finalize_kernel(const float* __restrict__ gamma,
                                   const float* __restrict__ beta,
                                   const float* __restrict__ Wgcn,
                                   const float* __restrict__ bgcn,
                                   const float* __restrict__ Wih,
                                   const float* __restrict__ bih)
{
    __shared__ float s_sum[32], s_sq[32];
    const int tid = threadIdx.x;
    if (tid < 64) {
        float a = 0.f;
        for (int bk = 0; bk < NB_STAT; ++bk) a += g_part[bk * 64 + tid];
        if (tid < 32) s_sum[tid] = a; else s_sq[tid - 32] = a;
    }
    __syncthreads();
    if (tid < 32) {
        const float M    = (float)NROWS;
        const float mean = s_sum[tid] / M;
        const float var  = s_sq[tid] / M - mean * mean;
        const float aK   = gamma[tid] * (1.0f / sqrtf(var + 1e-5f));
        g_bnA[tid] = aK;
        g_bnC[tid] = beta[tid] - mean * aK;
    }
    for (int idx = tid; idx < FEAT * G3; idx += blockDim.x) {
        const int f = idx / G3, j = idx % G3;
        float acc = 0.f;
        #pragma unroll 8
        for (int c = 0; c < 32; ++c) acc += Wgcn[f * 32 + c] * Wih[c * G3 + j];
        g_Wcomb[idx] = acc;
    }
    if (tid < G3) {
        float acc = bih[tid];
        #pragma unroll 8
        for (int c = 0; c < 32; ++c) acc += bgcn[c] * Wih[c * G3 + tid];
        g_bcomb[tid] = acc;
    }
}

// ============================================================
// Kernel 3: dense adj -> packed ELL (deterministic ballot order)
// ============================================================
__global__ void build_ell_kernel(const float* __restrict__ adj)
{
    const int warp = (blockIdx.x * blockDim.x + threadIdx.x) >> 5;
    const int lane = threadIdx.x & 31;
    const float* row = adj + (size_t)warp * N_NODES;
    const int base = warp * MAXD;
    int cnt = 0; float wsum = 0.f;
    for (int i = 0; i < N_NODES / 32; ++i) {
        const int c = i * 32 + lane;
        const float v = row[c];
        wsum += v;
        const unsigned mask = __ballot_sync(0xffffffffu, v != 0.0f);
        if (v != 0.0f) {
            const int pos = cnt + __popc(mask & ((1u << lane) - 1u));
            if (pos < MAXD) g_ell_cv[base + pos] = make_int2(c, __float_as_int(v));
        }
        cnt += __popc(mask);
    }
    #pragma unroll
    for (int o = 16; o > 0; o >>= 1) wsum += __shfl_xor_sync(0xffffffffu, wsum, o);
    if (lane == 0) {
        g_row_len[warp]  = cnt < MAXD ? cnt : MAXD;
        g_row_wsum[warp] = wsum;
    }
}

// ============================================================
// Kernel 4: aggregation for ALL (b,t) in parallel (no scan dep)
// grid (64 node-blocks, 32 bt), warp = feature lane, 8 nodes/warp
// ============================================================
__global__ void __launch_bounds__(THREADS)
agg_kernel(const float* __restrict__ x)
{
    const int lane = threadIdx.x & 31;
    const int wid  = threadIdx.x >> 5;
    const int bt   = blockIdx.y;
    const float* xbt = x + (size_t)bt * N_NODES * FEAT;
    const float bnA = g_bnA[lane];
    const float bnC = g_bnC[lane];

    #pragma unroll 1
    for (int mm = 0; mm < 8; ++mm) {
        const int m = blockIdx.x * NPB + wid * 8 + mm;
        const int len = g_row_len[m];
        const int2* cv = g_ell_cv + m * MAXD;
        float s0 = 0.f, s1 = 0.f, s2 = 0.f, s3 = 0.f;
        int k = 0;
        for (; k + 3 < len; k += 4) {
            const int2 e0 = cv[k], e1 = cv[k + 1], e2 = cv[k + 2], e3 = cv[k + 3];
            s0 += __int_as_float(e0.y) * xbt[e0.x * FEAT + lane];
            s1 += __int_as_float(e1.y) * xbt[e1.x * FEAT + lane];
            s2 += __int_as_float(e2.y) * xbt[e2.x * FEAT + lane];
            s3 += __int_as_float(e3.y) * xbt[e3.x * FEAT + lane];
        }
        for (; k < len; ++k) {
            const int2 e = cv[k];
            s0 += __int_as_float(e.y) * xbt[e.x * FEAT + lane];
        }
        const float a = (s0 + s1) + (s2 + s3);
        g_ya[((size_t)bt * N_NODES + m) * FEAT + lane] = bnA * a + bnC * g_row_wsum[m];
    }
}

// ============================================================
// Kernel 5: GRU scan, f32x2 packed combined GEMM
// block = 64 nodes x 1 batch, 256 threads, 2 blocks/SM
// ============================================================
#define LD64(p) (*reinterpret_cast<const unsigned long long*>(p))

#define FMA8(ACC, W0, W1)                                   \
    ACC[0][0] = fma2(W0, aP0, ACC[0][0]);                   \
    ACC[0][1] = fma2(W0, aP1, ACC[0][1]);                   \
    ACC[0][2] = fma2(W0, aP2, ACC[0][2]);                   \
    ACC[0][3] = fma2(W0, aP3, ACC[0][3]);                   \
    ACC[1][0] = fma2(W1, aP0, ACC[1][0]);                   \
    ACC[1][1] = fma2(W1, aP1, ACC[1][1]);                   \
    ACC[1][2] = fma2(W1, aP2, ACC[1][2]);                   \
    ACC[1][3] = fma2(W1, aP3, ACC[1][3]);

#define KSTEP(K, ACCN) {                                                        \
    const float4 av = *(const float4*)(sA + (K) * SA_STRIDE + m0);              \
    const unsigned long long aP0 = pack2(av.x), aP1 = pack2(av.y),              \
                             aP2 = pack2(av.z), aP3 = pack2(av.w);              \
    const float* wr = sW + (K) * G3 + k0;                                       \
    unsigned long long w0, w1;                                                  \
    w0 = LD64(wr);        w1 = LD64(wr + 2);    FMA8(accR, w0, w1)              \
    w0 = LD64(wr + 64);   w1 = LD64(wr + 66);   FMA8(accZ, w0, w1)              \
    w0 = LD64(wr + 128);  w1 = LD64(wr + 130);  FMA8(ACCN, w0, w1)              \
}

__global__ void __launch_bounds__(THREADS, 2)
gru_kernel(const float* __restrict__ Whh,
           const float* __restrict__ bhh,
           const float* __restrict__ Wd,
           const float* __restrict__ bd,
           float* __restrict__ out)
{
    extern __shared__ float sm[];
    float* sW   = sm;                         // [96][192] rows 0-31 Wcomb, 32-95 Whh
    float* sA   = sW + 96 * G3;               // [96][68]  rows 0-31 ya^T,  32-95 h^T
    float* sBrz = sA + 96 * SA_STRIDE;        // [128]  (bcomb+bhh) for r,z
    float* sBni = sBrz + 128;                 // [64]
    float* sBnh = sBni + 64;                  // [64]
    float* sWd  = sBnh + 64;                  // [64]

    const int tid = threadIdx.x;
    const int b   = blockIdx.x >> 6;
    const int gm0 = (blockIdx.x & 63) * NPB;

    for (int i = tid; i < 96 * G3; i += THREADS) {
        const int row = i / G3;
        sW[i] = (row < 32) ? g_Wcomb[i] : Whh[i - 32 * G3];
    }
    for (int i = tid; i < 64 * SA_STRIDE; i += THREADS) sA[32 * SA_STRIDE + i] = 0.0f;
    if (tid < 64) {
        sBrz[tid]      = g_bcomb[tid]       + bhh[tid];
        sBrz[64 + tid] = g_bcomb[64 + tid]  + bhh[64 + tid];
        sBni[tid]      = g_bcomb[128 + tid];
        sBnh[tid]      = bhh[128 + tid];
        sWd[tid]       = Wd[tid];
    }

    const int m0 = (tid & 15) * 4;
    const int k0 = (tid >> 4) * 4;
    const float bdv = bd[0];
    __syncthreads();

    for (int t = 0; t < TSTEPS; ++t) {
        // ---- load ya tile [64 nodes][32 f] and transpose into sA rows 0..31 ----
        const float* yat = g_ya + ((size_t)(b * TSTEPS + t) * N_NODES + gm0) * FEAT;
        #pragma unroll
        for (int rep = 0; rep < 2; ++rep) {
            const int idx = tid + rep * THREADS;
            const int m = idx >> 3, f0 = (idx & 7) * 4;
            const float4 v = *(const float4*)(yat + m * FEAT + f0);
            sA[(f0 + 0) * SA_STRIDE + m] = v.x;
            sA[(f0 + 1) * SA_STRIDE + m] = v.y;
            sA[(f0 + 2) * SA_STRIDE + m] = v.z;
            sA[(f0 + 3) * SA_STRIDE + m] = v.w;
        }
        __syncthreads();

        // ---- init accumulators from biases ----
        unsigned long long accR[2][4], accZ[2][4], accNi[2][4], accNh[2][4];
        {
            const unsigned long long bR0 = LD64(sBrz + k0),       bR1 = LD64(sBrz + k0 + 2);
            const unsigned long long bZ0 = LD64(sBrz + 64 + k0),  bZ1 = LD64(sBrz + 64 + k0 + 2);
            const unsigned long long bI0 = LD64(sBni + k0),       bI1 = LD64(sBni + k0 + 2);
            const unsigned long long bH0 = LD64(sBnh + k0),       bH1 = LD64(sBnh + k0 + 2);
            #pragma unroll
            for (int mm = 0; mm < 4; ++mm) {
                accR[0][mm] = bR0;  accR[1][mm] = bR1;
                accZ[0][mm] = bZ0;  accZ[1][mm] = bZ1;
                accNi[0][mm] = bI0; accNi[1][mm] = bI1;
                accNh[0][mm] = bH0; accNh[1][mm] = bH1;
            }
        }

        // ---- combined GEMM: k 0..31 over ya (n->Ni), k 32..95 over h (n->Nh) ----
        #pragma unroll 4
        for (int k = 0; k < 32; ++k) KSTEP(k, accNi)
        #pragma unroll 4
        for (int k = 32; k < 96; ++k) KSTEP(k, accNh)

        // ---- GRU gates ----
        float hn[4][4];
        #pragma unroll
        for (int kkp = 0; kkp < 2; ++kkp)
            #pragma unroll
            for (int mm = 0; mm < 4; ++mm) {
                const float2 rv = unpack2(accR[kkp][mm]);
                const float2 zv = unpack2(accZ[kkp][mm]);
                const float2 iv = unpack2(accNi[kkp][mm]);
                const float2 hv = unpack2(accNh[kkp][mm]);
                {
                    const int kk = kkp * 2;
                    const float hold = sA[(32 + k0 + kk) * SA_STRIDE + m0 + mm];
                    const float r = sigm(rv.x), z = sigm(zv.x);
                    const float n = tanhf(iv.x + r * hv.x);
                    hn[kk][mm] = (1.0f - z) * n + z * hold;
                }
                {
                    const int kk = kkp * 2 + 1;
                    const float hold = sA[(32 + k0 + kk) * SA_STRIDE + m0 + mm];
                    const float r = sigm(rv.y), z = sigm(zv.y);
                    const float n = tanhf(iv.y + r * hv.y);
                    hn[kk][mm] = (1.0f - z) * n + z * hold;
                }
            }
        __syncthreads();     // all reads of sA (a + h_old) complete

        #pragma unroll
        for (int kk = 0; kk < 4; ++kk) {
            float4 v;
            v.x = hn[kk][0]; v.y = hn[kk][1]; v.z = hn[kk][2]; v.w = hn[kk][3];
            *(float4*)(sA + (32 + k0 + kk) * SA_STRIDE + m0) = v;
        }
        __syncthreads();     // new h visible

        // ---- dense head ----
        if (tid < NPB) {
            float acc = bdv;
            #pragma unroll 8
            for (int k = 0; k < HDIM; ++k)
                acc += sA[(32 + k) * SA_STRIDE + tid] * sWd[k];
            out[(size_t)(b * TSTEPS + t) * N_NODES + gm0 + tid] = acc;
        }
        // no sync needed: head reads rows 32-95; next ya store hits rows 0-31,
        // and the next __syncthreads() (after transpose) orders everything.
        __syncthreads();
    }
}

// ============================================================
// launch
// ============================================================
extern "C" void kernel_launch(void* const* d_in, const int* in_sizes, int n_in,
                              void* d_out, int out_size)
{
    const float* x     = (const float*)d_in[0];
    const float* adj   = (const float*)d_in[1];
    const float* gamma = (const float*)d_in[2];
    const float* beta  = (const float*)d_in[3];
    const float* Wgcn  = (const float*)d_in[4];
    const float* bgcn  = (const float*)d_in[5];
    const float* Wih   = (const float*)d_in[6];
    const float* Whh   = (const float*)d_in[7];
    const float* bih   = (const float*)d_in[8];
    const float* bhh   = (const float*)d_in[9];
    const float* Wd    = (const float*)d_in[10];
    const float* bd    = (const float*)d_in[11];
    float* out = (float*)d_out;

    const int smem_bytes = (96 * G3 + 96 * SA_STRIDE + 128 + 64 + 64 + 64) * (int)sizeof(float);
    cudaFuncSetAttribute(gru_kernel, cudaFuncAttributeMaxDynamicSharedMemorySize, smem_bytes);

    bn_partial_kernel<<<NB_STAT, THREADS>>>(x);
    bn_finalize_kernel<<<1, THREADS>>>(gamma, beta, Wgcn, bgcn, Wih, bih);
    build_ell_kernel<<<(N_NODES * 32) / THREADS, THREADS>>>(adj);
    {
        dim3 g(N_NODES / NPB, NBT);
        agg_kernel<<<g, THREADS>>>(x);
    }
    gru_kernel<<<BATCH * (N_NODES / NPB), THREADS, smem_bytes>>>(Whh, bhh, Wd, bd, out);
}

// round 3
// speedup vs baseline: 1.7268x; 1.6807x over previous
#include <cuda_runtime.h>

#define N_NODES 4096
#define FEAT    32
#define G3      192
#define HDIM    64
#define BATCH   4
#define TSTEPS  8
#define NBT     (BATCH*TSTEPS)           // 32
#define MAXD    128
#define NROWS   (NBT*N_NODES)            // 131072
#define SAS     132                       // sA row stride (128 nodes + pad)
#define GRU_THREADS 512
#define GRU_NPB     128

// -------- static device scratch --------
__device__ int   g_row_len[N_NODES];
__device__ float g_row_wsum[N_NODES];
__device__ int2  g_ell_cv[N_NODES * MAXD];
__device__ float g_bnA[FEAT];
__device__ float g_bnC[FEAT];
__device__ float g_Wcomb[FEAT * G3];
__device__ float g_bcomb[G3];
__device__ float g_partN[N_NODES * 64];         // per-node BN partials [n][64]
__device__ float g_xT[(size_t)N_NODES * NBT * FEAT];   // [n][bt][f] 16MB
__device__ float g_ya[(size_t)NROWS * FEAT];           // [bt][n][f]  16MB

// -------- f32x2 helpers --------
__device__ __forceinline__ unsigned long long pack2(float a) {
    unsigned long long r;
    asm("mov.b64 %0, {%1, %1};" : "=l"(r) : "f"(a));
    return r;
}
__device__ __forceinline__ float2 unpack2(unsigned long long v) {
    float2 r;
    asm("mov.b64 {%0, %1}, %2;" : "=f"(r.x), "=f"(r.y) : "l"(v));
    return r;
}
__device__ __forceinline__ unsigned long long fma2(unsigned long long a,
                                                   unsigned long long b,
                                                   unsigned long long c) {
    unsigned long long d;
    asm("fma.rn.f32x2 %0, %1, %2, %3;" : "=l"(d) : "l"(a), "l"(b), "l"(c));
    return d;
}
__device__ __forceinline__ float sigm(float v) { return 1.0f / (1.0f + __expf(-v)); }

// ============================================================
// Kernel 1: dense adj -> packed ELL (deterministic ballot order)
// ============================================================
__global__ void build_ell_kernel(const float* __restrict__ adj)
{
    const int warp = (blockIdx.x * blockDim.x + threadIdx.x) >> 5;
    const int lane = threadIdx.x & 31;
    const float* row = adj + (size_t)warp * N_NODES;
    const int base = warp * MAXD;
    int cnt = 0; float wsum = 0.f;
    for (int i = 0; i < N_NODES / 32; ++i) {
        const int c = i * 32 + lane;
        const float v = row[c];
        wsum += v;
        const unsigned mask = __ballot_sync(0xffffffffu, v != 0.0f);
        if (v != 0.0f) {
            const int pos = cnt + __popc(mask & ((1u << lane) - 1u));
            if (pos < MAXD) g_ell_cv[base + pos] = make_int2(c, __float_as_int(v));
        }
        cnt += __popc(mask);
    }
    #pragma unroll
    for (int o = 16; o > 0; o >>= 1) wsum += __shfl_xor_sync(0xffffffffu, wsum, o);
    if (lane == 0) {
        g_row_len[warp]  = cnt < MAXD ? cnt : MAXD;
        g_row_wsum[warp] = wsum;
    }
}

// ============================================================
// Kernel 2: transpose x[bt][n][f] -> xT[n][bt][f], fused with
// per-node BN partial sums (deterministic).
// One block = one node. thread: bt=tid>>3, f0=(tid&7)*4.
// ============================================================
__global__ void __launch_bounds__(256)
transpose_bn_kernel(const float* __restrict__ x)
{
    const int n   = blockIdx.x;
    const int tid = threadIdx.x;
    const int bt  = tid >> 3;
    const int f0  = (tid & 7) * 4;
    const int lane = tid & 31;
    const int w    = tid >> 5;

    const float4 v = *(const float4*)(x + ((size_t)bt * N_NODES + n) * FEAT + f0);
    *(float4*)(g_xT + (size_t)n * (NBT * FEAT) + bt * FEAT + f0) = v;

    // BN partials: reduce over the 4 bt-locals within each warp (lane bits 3,4)
    float s0 = v.x, s1 = v.y, s2 = v.z, s3 = v.w;
    float q0 = v.x * v.x, q1 = v.y * v.y, q2 = v.z * v.z, q3 = v.w * v.w;
    #pragma unroll
    for (int o = 8; o <= 16; o <<= 1) {
        s0 += __shfl_xor_sync(0xffffffffu, s0, o);
        s1 += __shfl_xor_sync(0xffffffffu, s1, o);
        s2 += __shfl_xor_sync(0xffffffffu, s2, o);
        s3 += __shfl_xor_sync(0xffffffffu, s3, o);
        q0 += __shfl_xor_sync(0xffffffffu, q0, o);
        q1 += __shfl_xor_sync(0xffffffffu, q1, o);
        q2 += __shfl_xor_sync(0xffffffffu, q2, o);
        q3 += __shfl_xor_sync(0xffffffffu, q3, o);
    }
    __shared__ float sh[8][64];
    if (lane < 8) {
        sh[w][f0 + 0]      = s0;  sh[w][f0 + 1]      = s1;
        sh[w][f0 + 2]      = s2;  sh[w][f0 + 3]      = s3;
        sh[w][32 + f0 + 0] = q0;  sh[w][32 + f0 + 1] = q1;
        sh[w][32 + f0 + 2] = q2;  sh[w][32 + f0 + 3] = q3;
    }
    __syncthreads();
    if (tid < 64) {
        float a = 0.f;
        #pragma unroll
        for (int i = 0; i < 8; ++i) a += sh[i][tid];
        g_partN[n * 64 + tid] = a;
    }
}

// ============================================================
// Kernel 3: finalize BN affine + Wcomb/bcomb (single block)
// ============================================================
__global__ void __launch_bounds__(256)
finalize_kernel(const float* __restrict__ gamma,
                const float* __restrict__ beta,
                const float* __restrict__ Wgcn,
                const float* __restrict__ bgcn,
                const float* __restrict__ Wih,
                const float* __restrict__ bih)
{
    __shared__ float red[4][64];
    __shared__ float s_sum[32], s_sq[32];
    const int tid = threadIdx.x;
    {
        float a = 0.f;
        const int c = tid & 63;
        for (int n = tid >> 6; n < N_NODES; n += 4) a += g_partN[n * 64 + c];
        red[tid >> 6][c] = a;
    }
    __syncthreads();
    if (tid < 64) {
        const float a = red[0][tid] + red[1][tid] + red[2][tid] + red[3][tid];
        if (tid < 32) s_sum[tid] = a; else s_sq[tid - 32] = a;
    }
    __syncthreads();
    if (tid < 32) {
        const float M    = (float)NROWS;
        const float mean = s_sum[tid] / M;
        const float var  = s_sq[tid] / M - mean * mean;
        const float aK   = gamma[tid] * (1.0f / sqrtf(var + 1e-5f));
        g_bnA[tid] = aK;
        g_bnC[tid] = beta[tid] - mean * aK;
    }
    for (int idx = tid; idx < FEAT * G3; idx += blockDim.x) {
        const int f = idx / G3, j = idx % G3;
        float acc = 0.f;
        #pragma unroll 8
        for (int c = 0; c < 32; ++c) acc += Wgcn[f * 32 + c] * Wih[c * G3 + j];
        g_Wcomb[idx] = acc;
    }
    if (tid < G3) {
        float acc = bih[tid];
        #pragma unroll 8
        for (int c = 0; c < 32; ++c) acc += bgcn[c] * Wih[c * G3 + tid];
        g_bcomb[tid] = acc;
    }
}

// ============================================================
// Kernel 4: aggregation. One block = one node, all 32 bt.
// thread: f = tid&31, bt0 = tid>>5 (handles bt0, bt0+8, +16, +24)
// ============================================================
__global__ void __launch_bounds__(256)
agg_kernel()
{
    const int m   = blockIdx.x;
    const int tid = threadIdx.x;
    const int f   = tid & 31;
    const int bt0 = tid >> 5;

    const int len = g_row_len[m];
    const float wsum = g_row_wsum[m];
    const int2* cv = g_ell_cv + m * MAXD;

    float a0 = 0.f, a1 = 0.f, a2 = 0.f, a3 = 0.f;
    const int off = bt0 * FEAT + f;

    int k = 0;
    for (; k + 1 < len; k += 2) {
        const int2 e0 = cv[k], e1 = cv[k + 1];
        const float w0 = __int_as_float(e0.y), w1 = __int_as_float(e1.y);
        const float* p0 = g_xT + (size_t)e0.x * (NBT * FEAT) + off;
        const float* p1 = g_xT + (size_t)e1.x * (NBT * FEAT) + off;
        const float v00 = p0[0],    v01 = p0[256],  v02 = p0[512],  v03 = p0[768];
        const float v10 = p1[0],    v11 = p1[256],  v12 = p1[512],  v13 = p1[768];
        a0 += w0 * v00; a1 += w0 * v01; a2 += w0 * v02; a3 += w0 * v03;
        a0 += w1 * v10; a1 += w1 * v11; a2 += w1 * v12; a3 += w1 * v13;
    }
    if (k < len) {
        const int2 e = cv[k];
        const float w = __int_as_float(e.y);
        const float* p = g_xT + (size_t)e.x * (NBT * FEAT) + off;
        a0 += w * p[0]; a1 += w * p[256]; a2 += w * p[512]; a3 += w * p[768];
    }

    const float A = g_bnA[f];
    const float C = g_bnC[f] * wsum;
    g_ya[((size_t)(bt0 +  0) * N_NODES + m) * FEAT + f] = A * a0 + C;
    g_ya[((size_t)(bt0 +  8) * N_NODES + m) * FEAT + f] = A * a1 + C;
    g_ya[((size_t)(bt0 + 16) * N_NODES + m) * FEAT + f] = A * a2 + C;
    g_ya[((size_t)(bt0 + 24) * N_NODES + m) * FEAT + f] = A * a3 + C;
}

// ============================================================
// Kernel 5: GRU scan. 512 threads, 128 nodes/block, 128 blocks.
// Permuted weight layout: sW[k][kt*12 + g*4 + j] = W[k][g*64+kt*4+j]
// ============================================================
#define LD64(p) (*reinterpret_cast<const unsigned long long*>(p))

#define FMA8(ACC, W0, W1)                                   \
    ACC[0][0] = fma2(W0, aP0, ACC[0][0]);                   \
    ACC[0][1] = fma2(W0, aP1, ACC[0][1]);                   \
    ACC[0][2] = fma2(W0, aP2, ACC[0][2]);                   \
    ACC[0][3] = fma2(W0, aP3, ACC[0][3]);                   \
    ACC[1][0] = fma2(W1, aP0, ACC[1][0]);                   \
    ACC[1][1] = fma2(W1, aP1, ACC[1][1]);                   \
    ACC[1][2] = fma2(W1, aP2, ACC[1][2]);                   \
    ACC[1][3] = fma2(W1, aP3, ACC[1][3]);

#define KSTEP(K, ACCN) {                                                        \
    const float4 av = *(const float4*)(sA + (K) * SAS + m0);                    \
    const unsigned long long aP0 = pack2(av.x), aP1 = pack2(av.y),              \
                             aP2 = pack2(av.z), aP3 = pack2(av.w);              \
    const float* wr = sW + (K) * G3 + kt12;                                     \
    const ulonglong2 wR = *(const ulonglong2*)(wr);                             \
    const ulonglong2 wZ = *(const ulonglong2*)(wr + 4);                         \
    const ulonglong2 wN = *(const ulonglong2*)(wr + 8);                         \
    FMA8(accR, wR.x, wR.y)                                                      \
    FMA8(accZ, wZ.x, wZ.y)                                                      \
    FMA8(ACCN, wN.x, wN.y)                                                      \
}

__global__ void __launch_bounds__(GRU_THREADS, 1)
gru_kernel(const float* __restrict__ Whh,
           const float* __restrict__ bhh,
           const float* __restrict__ Wd,
           const float* __restrict__ bd,
           float* __restrict__ out)
{
    extern __shared__ float sm[];
    float* sW   = sm;                         // [96][192] permuted; rows 0-31 Wcomb, 32-95 Whh
    float* sA   = sW + 96 * G3;               // [96][SAS] rows 0-31 ya^T, 32-95 h^T
    float* sBrz = sA + 96 * SAS;              // [128]
    float* sBni = sBrz + 128;                 // [64]
    float* sBnh = sBni + 64;                  // [64]
    float* sWd  = sBnh + 64;                  // [64]

    const int tid = threadIdx.x;
    const int b   = blockIdx.x >> 5;
    const int gm0 = (blockIdx.x & 31) * GRU_NPB;

    // load + permute weights
    for (int i = tid; i < 96 * G3; i += GRU_THREADS) {
        const int row = i / G3, cc = i % G3;
        const int ktl = cc / 12, rem = cc % 12;
        const int g = rem >> 2, j = rem & 3;
        const int ocol = g * 64 + ktl * 4 + j;
        sW[i] = (row < 32) ? g_Wcomb[row * G3 + ocol] : Whh[(row - 32) * G3 + ocol];
    }
    for (int i = tid; i < 64 * SAS; i += GRU_THREADS) sA[32 * SAS + i] = 0.0f;  // h0 = 0
    if (tid < 64) {
        sBrz[tid]      = g_bcomb[tid]      + bhh[tid];
        sBrz[64 + tid] = g_bcomb[64 + tid] + bhh[64 + tid];
        sBni[tid]      = g_bcomb[128 + tid];
        sBnh[tid]      = bhh[128 + tid];
        sWd[tid]       = Wd[tid];
    }

    const int m0   = (tid & 15) * 4 + (tid >> 8) * 64;
    const int ktl  = (tid >> 4) & 15;
    const int k0   = ktl * 4;
    const int kt12 = ktl * 12;
    const float bdv = bd[0];
    __syncthreads();

    for (int t = 0; t < TSTEPS; ++t) {
        // ---- load ya tile [128 nodes][32 f], transpose into sA rows 0..31 ----
        const float* yat = g_ya + ((size_t)(b * TSTEPS + t) * N_NODES + gm0) * FEAT;
        #pragma unroll
        for (int rep = 0; rep < 2; ++rep) {
            const int idx = tid + rep * GRU_THREADS;
            const int m = idx >> 3, f0 = (idx & 7) * 4;
            const float4 v = *(const float4*)(yat + m * FEAT + f0);
            sA[(f0 + 0) * SAS + m] = v.x;
            sA[(f0 + 1) * SAS + m] = v.y;
            sA[(f0 + 2) * SAS + m] = v.z;
            sA[(f0 + 3) * SAS + m] = v.w;
        }
        __syncthreads();

        // ---- init accumulators from biases ----
        unsigned long long accR[2][4], accZ[2][4], accNi[2][4], accNh[2][4];
        {
            const unsigned long long bR0 = LD64(sBrz + k0),      bR1 = LD64(sBrz + k0 + 2);
            const unsigned long long bZ0 = LD64(sBrz + 64 + k0), bZ1 = LD64(sBrz + 64 + k0 + 2);
            const unsigned long long bI0 = LD64(sBni + k0),      bI1 = LD64(sBni + k0 + 2);
            const unsigned long long bH0 = LD64(sBnh + k0),      bH1 = LD64(sBnh + k0 + 2);
            #pragma unroll
            for (int mm = 0; mm < 4; ++mm) {
                accR[0][mm] = bR0;  accR[1][mm] = bR1;
                accZ[0][mm] = bZ0;  accZ[1][mm] = bZ1;
                accNi[0][mm] = bI0; accNi[1][mm] = bI1;
                accNh[0][mm] = bH0; accNh[1][mm] = bH1;
            }
        }

        // ---- combined GEMM over k: ya rows then h rows ----
        #pragma unroll 4
        for (int k = 0; k < 32; ++k) KSTEP(k, accNi)
        #pragma unroll 4
        for (int k = 32; k < 96; ++k) KSTEP(k, accNh)

        // ---- GRU gates ----
        float hn[4][4];
        #pragma unroll
        for (int kkp = 0; kkp < 2; ++kkp)
            #pragma unroll
            for (int mm = 0; mm < 4; ++mm) {
                const float2 rv = unpack2(accR[kkp][mm]);
                const float2 zv = unpack2(accZ[kkp][mm]);
                const float2 iv = unpack2(accNi[kkp][mm]);
                const float2 hv = unpack2(accNh[kkp][mm]);
                {
                    const int kk = kkp * 2;
                    const float hold = sA[(32 + k0 + kk) * SAS + m0 + mm];
                    const float r = sigm(rv.x), z = sigm(zv.x);
                    const float n = tanhf(iv.x + r * hv.x);
                    hn[kk][mm] = (1.0f - z) * n + z * hold;
                }
                {
                    const int kk = kkp * 2 + 1;
                    const float hold = sA[(32 + k0 + kk) * SAS + m0 + mm];
                    const float r = sigm(rv.y), z = sigm(zv.y);
                    const float n = tanhf(iv.y + r * hv.y);
                    hn[kk][mm] = (1.0f - z) * n + z * hold;
                }
            }
        __syncthreads();   // all reads of sA done

        #pragma unroll
        for (int kk = 0; kk < 4; ++kk) {
            float4 v;
            v.x = hn[kk][0]; v.y = hn[kk][1]; v.z = hn[kk][2]; v.w = hn[kk][3];
            *(float4*)(sA + (32 + k0 + kk) * SAS + m0) = v;
        }
        __syncthreads();   // new h visible

        // ---- dense head ----
        if (tid < GRU_NPB) {
            float acc = bdv;
            #pragma unroll 8
            for (int k = 0; k < HDIM; ++k)
                acc += sA[(32 + k) * SAS + tid] * sWd[k];
            out[(size_t)(b * TSTEPS + t) * N_NODES + gm0 + tid] = acc;
        }
        __syncthreads();
    }
}

// ============================================================
// launch
// ============================================================
extern "C" void kernel_launch(void* const* d_in, const int* in_sizes, int n_in,
                              void* d_out, int out_size)
{
    const float* x     = (const float*)d_in[0];
    const float* adj   = (const float*)d_in[1];
    const float* gamma = (const float*)d_in[2];
    const float* beta  = (const float*)d_in[3];
    const float* Wgcn  = (const float*)d_in[4];
    const float* bgcn  = (const float*)d_in[5];
    const float* Wih   = (const float*)d_in[6];
    const float* Whh   = (const float*)d_in[7];
    const float* bih   = (const float*)d_in[8];
    const float* bhh   = (const float*)d_in[9];
    const float* Wd    = (const float*)d_in[10];
    const float* bd    = (const float*)d_in[11];
    float* out = (float*)d_out;

    const int smem_bytes = (96 * G3 + 96 * SAS + 128 + 64 + 64 + 64) * (int)sizeof(float);
    cudaFuncSetAttribute(gru_kernel, cudaFuncAttributeMaxDynamicSharedMemorySize, smem_bytes);

    build_ell_kernel<<<N_NODES / 8, 256>>>(adj);
    transpose_bn_kernel<<<N_NODES, 256>>>(x);
    finalize_kernel<<<1, 256>>>(gamma, beta, Wgcn, bgcn, Wih, bih);
    agg_kernel<<<N_NODES, 256>>>();
    gru_kernel<<<BATCH * (N_NODES / GRU_NPB), GRU_THREADS, smem_bytes>>>(Whh, bhh, Wd, bd, out);
}